// round 7
// baseline (speedup 1.0000x reference)
#include <cuda_runtime.h>
#include <cuda_bf16.h>
#include <math.h>

// Problem constants (fixed by the reference)
#define BB   4
#define TT   2048
#define MM   16
#define DD   512
#define HH   8
#define DFF  2048
#define WIN  128
#define LL   (MM + TT)          // 2064
#define NROWS (BB * LL)         // 8256
#define DH   64

// ---------------------------------------------------------------------------
// Scratch
// ---------------------------------------------------------------------------
__device__ float g_x2  [(size_t)NROWS * DD];
__device__ float g_qkv [(size_t)NROWS * 3 * DD];
__device__ float g_attn[(size_t)NROWS * DD];
__device__ float g_xres[(size_t)NROWS * DD];
__device__ float g_hln [(size_t)NROWS * DD];
__device__ float g_ffn [(size_t)NROWS * DFF];

// ---------------------------------------------------------------------------
// LayerNorm over D=512. One block (128 threads) per row.
// ---------------------------------------------------------------------------
__global__ void ln_kernel(const float* __restrict__ x,
                          const float* __restrict__ g,
                          const float* __restrict__ b,
                          float* __restrict__ y)
{
    int row = blockIdx.x;
    int t = threadIdx.x;
    const float4* xr = (const float4*)(x + (size_t)row * DD);
    float4 v = xr[t];
    float s  = v.x + v.y + v.z + v.w;
    float ss = v.x*v.x + v.y*v.y + v.z*v.z + v.w*v.w;

    int lane = t & 31, wid = t >> 5;
    #pragma unroll
    for (int o = 16; o > 0; o >>= 1) {
        s  += __shfl_xor_sync(0xffffffffu, s,  o);
        ss += __shfl_xor_sync(0xffffffffu, ss, o);
    }
    __shared__ float sh[8];
    if (lane == 0) { sh[wid] = s; sh[wid + 4] = ss; }
    __syncthreads();
    s  = sh[0] + sh[1] + sh[2] + sh[3];
    ss = sh[4] + sh[5] + sh[6] + sh[7];

    float mu  = s * (1.0f / DD);
    float var = ss * (1.0f / DD) - mu * mu;
    float inv = rsqrtf(var + 1e-5f);

    float4 gg = ((const float4*)g)[t];
    float4 bb = ((const float4*)b)[t];
    float4 o4;
    o4.x = (v.x - mu) * inv * gg.x + bb.x;
    o4.y = (v.y - mu) * inv * gg.y + bb.y;
    o4.z = (v.z - mu) * inv * gg.z + bb.z;
    o4.w = (v.w - mu) * inv * gg.w + bb.w;
    ((float4*)(y + (size_t)row * DD))[t] = o4;
}

// ---------------------------------------------------------------------------
// TF32 tensor-core GEMM (fast-tf32: raw fp32 bits, HW truncates to tf32).
// C[N,Mo] = A[N,K] @ W[Mo,K]^T + bias (+res) (+gelu)
// Block tile 128x128, BK=16, 256 threads (8 warps, 2x4, warp tile 64x32),
// mma.sync.m16n8k8. 2-stage LDG->reg->STS pipeline.
// Smem k-tiles use a column permutation phys=(c&3)*4+(c>>2) so each thread's
// fragment elements for BOTH k-groups are one contiguous LDS.128.
// ---------------------------------------------------------------------------
__device__ __forceinline__ void mma_tf32(float* c,
                                         unsigned a0, unsigned a1, unsigned a2, unsigned a3,
                                         unsigned b0, unsigned b1) {
    asm volatile(
        "mma.sync.aligned.m16n8k8.row.col.f32.tf32.tf32.f32 "
        "{%0,%1,%2,%3}, {%4,%5,%6,%7}, {%8,%9}, {%0,%1,%2,%3};"
        : "+f"(c[0]), "+f"(c[1]), "+f"(c[2]), "+f"(c[3])
        : "r"(a0), "r"(a1), "r"(a2), "r"(a3), "r"(b0), "r"(b1));
}

template<int ACT>
__global__ __launch_bounds__(256, 2) void mma_gemm(
    const float* __restrict__ A,
    const float* __restrict__ W,
    const float* __restrict__ bias,
    const float* __restrict__ res,
    float* __restrict__ C,
    int N, int Mo, int K)
{
    __shared__ __align__(16) float As[2][128][20];
    __shared__ __align__(16) float Ws[2][128][20];

    int tid  = threadIdx.x;
    int lane = tid & 31;
    int wid  = tid >> 5;
    int wm   = wid >> 2;          // 0..1
    int wn   = wid & 3;           // 0..3
    int n0   = blockIdx.y * 128;
    int m0   = blockIdx.x * 128;

    int lr = tid >> 2;            // 0..63 (row this thread stages)
    int gg = tid & 3;             // k-chunk group 0..3 (logical cols 4g..4g+3)
    int lc = gg * 4;

    const float* Ap0 = A + (size_t)(n0 + lr)      * K + lc;
    const float* Ap1 = A + (size_t)(n0 + lr + 64) * K + lc;
    const float* Wp0 = W + (size_t)(m0 + lr)      * K + lc;
    const float* Wp1 = W + (size_t)(m0 + lr + 64) * K + lc;
    bool v0 = (n0 + lr)      < N;
    bool v1 = (n0 + lr + 64) < N;

    float acc[4][4][4];
    #pragma unroll
    for (int i = 0; i < 4; i++)
        #pragma unroll
        for (int j = 0; j < 4; j++)
            #pragma unroll
            for (int q = 0; q < 4; q++) acc[i][j][q] = 0.0f;

    int nIter = K >> 4;
    int lq = lane >> 2;      // 0..7
    int lk = lane & 3;       // 0..3

    const float4 z4 = make_float4(0.f, 0.f, 0.f, 0.f);
    float4 ra0, ra1, rw0, rw1;

    // permuted STS: logical col 4g+j -> phys col j*4+g
    #define STS_PERM(arr, bufi, r, v)                 \
        arr[bufi][r][gg]      = (v).x;                \
        arr[bufi][r][gg + 4]  = (v).y;                \
        arr[bufi][r][gg + 8]  = (v).z;                \
        arr[bufi][r][gg + 12] = (v).w;

    // prologue: tile 0 -> buf 0
    ra0 = v0 ? *(const float4*)Ap0 : z4;
    ra1 = v1 ? *(const float4*)Ap1 : z4;
    rw0 = *(const float4*)Wp0;
    rw1 = *(const float4*)Wp1;
    STS_PERM(As, 0, lr, ra0)
    STS_PERM(As, 0, lr + 64, ra1)
    STS_PERM(Ws, 0, lr, rw0)
    STS_PERM(Ws, 0, lr + 64, rw1)
    __syncthreads();

    int buf = 0;
    for (int it = 0; it < nIter; it++) {
        if (it + 1 < nIter) {
            int k0 = (it + 1) << 4;
            ra0 = v0 ? *(const float4*)(Ap0 + k0) : z4;
            ra1 = v1 ? *(const float4*)(Ap1 + k0) : z4;
            rw0 = *(const float4*)(Wp0 + k0);
            rw1 = *(const float4*)(Wp1 + k0);
        }

        // fragment loads: 12 x LDS.128 covering both k-groups
        uint4 aq[4][2];
        uint4 bq[4];
        #pragma unroll
        for (int am = 0; am < 4; am++) {
            int mr = wm * 64 + am * 16 + lq;
            aq[am][0] = *(const uint4*)&As[buf][mr][lk * 4];
            aq[am][1] = *(const uint4*)&As[buf][mr + 8][lk * 4];
        }
        #pragma unroll
        for (int an = 0; an < 4; an++) {
            int nr = wn * 32 + an * 8 + lq;
            bq[an] = *(const uint4*)&Ws[buf][nr][lk * 4];
        }
        // ks0: quad components .x (k=lk), .y (k=lk+4)
        #pragma unroll
        for (int am = 0; am < 4; am++)
            #pragma unroll
            for (int an = 0; an < 4; an++)
                mma_tf32(acc[am][an],
                         aq[am][0].x, aq[am][1].x, aq[am][0].y, aq[am][1].y,
                         bq[an].x, bq[an].y);
        // ks1: .z (k=lk+8), .w (k=lk+12)
        #pragma unroll
        for (int am = 0; am < 4; am++)
            #pragma unroll
            for (int an = 0; an < 4; an++)
                mma_tf32(acc[am][an],
                         aq[am][0].z, aq[am][1].z, aq[am][0].w, aq[am][1].w,
                         bq[an].z, bq[an].w);

        if (it + 1 < nIter) {
            int nb = buf ^ 1;
            STS_PERM(As, nb, lr, ra0)
            STS_PERM(As, nb, lr + 64, ra1)
            STS_PERM(Ws, nb, lr, rw0)
            STS_PERM(Ws, nb, lr + 64, rw1)
        }
        __syncthreads();
        buf ^= 1;
    }

    // epilogue
    #pragma unroll
    for (int am = 0; am < 4; am++) {
        #pragma unroll
        for (int an = 0; an < 4; an++) {
            int r0 = n0 + wm * 64 + am * 16 + lq;
            int c0 = m0 + wn * 32 + an * 8 + lk * 2;
            float b0 = bias[c0], b1 = bias[c0 + 1];
            #pragma unroll
            for (int half = 0; half < 2; half++) {
                int row = r0 + half * 8;
                if (row < N) {
                    float u0 = acc[am][an][half * 2 + 0] + b0;
                    float u1 = acc[am][an][half * 2 + 1] + b1;
                    if (ACT == 1) {
                        u0 = 0.5f * u0 * (1.0f + erff(u0 * 0.70710678118654752f));
                        u1 = 0.5f * u1 * (1.0f + erff(u1 * 0.70710678118654752f));
                    }
                    if (res) {
                        const float2 rr = *(const float2*)(res + (size_t)row * Mo + c0);
                        u0 += rr.x; u1 += rr.y;
                    }
                    *(float2*)(C + (size_t)row * Mo + c0) = make_float2(u0, u1);
                }
            }
        }
    }
    #undef STS_PERM
}

// ---------------------------------------------------------------------------
// Banded attention. One warp per (b,h,query). Online softmax, 4 keys/iter,
// float2 accesses.
// ---------------------------------------------------------------------------
__global__ void attn_kernel(const float* __restrict__ qkv,
                            float* __restrict__ out)
{
    int lane = threadIdx.x & 31;
    int wid  = threadIdx.x >> 5;
    int bh = blockIdx.x;
    int b = bh >> 3;
    int h = bh & 7;
    int i = blockIdx.y * 8 + wid;
    if (i >= LL) return;

    const float* base = qkv + (size_t)b * LL * (3 * DD);
    float2 q = *(const float2*)(base + (size_t)i * (3 * DD) + h * DH + 2 * lane);

    float m = -1e30f, dsum = 0.0f;
    float2 a = make_float2(0.f, 0.f);
    const float scale = 0.125f;           // 1/sqrt(64)

    int rA_lo, rA_hi, rB_lo, rB_hi;       // inclusive
    if (i < MM) {
        rA_lo = 0; rA_hi = i;
        rB_lo = 1; rB_hi = 0;             // empty
    } else {
        rA_lo = 0; rA_hi = MM - 1;
        rB_lo = (i - WIN + 1 > MM) ? (i - WIN + 1) : MM;
        rB_hi = i;
    }

    const int kstride = 3 * DD;
    for (int r = 0; r < 2; r++) {
        int lo = (r == 0) ? rA_lo : rB_lo;
        int hi = (r == 0) ? rA_hi : rB_hi;
        int j = lo;
        for (; j + 3 <= hi; j += 4) {
            const float* kp = base + (size_t)j * kstride + DD + h * DH + 2 * lane;
            float2 k0 = *(const float2*)(kp);
            float2 k1 = *(const float2*)(kp + kstride);
            float2 k2 = *(const float2*)(kp + 2 * kstride);
            float2 k3 = *(const float2*)(kp + 3 * kstride);
            float s0 = q.x * k0.x + q.y * k0.y;
            float s1 = q.x * k1.x + q.y * k1.y;
            float s2 = q.x * k2.x + q.y * k2.y;
            float s3 = q.x * k3.x + q.y * k3.y;
            #pragma unroll
            for (int o = 16; o > 0; o >>= 1) {
                s0 += __shfl_xor_sync(0xffffffffu, s0, o);
                s1 += __shfl_xor_sync(0xffffffffu, s1, o);
                s2 += __shfl_xor_sync(0xffffffffu, s2, o);
                s3 += __shfl_xor_sync(0xffffffffu, s3, o);
            }
            s0 *= scale; s1 *= scale; s2 *= scale; s3 *= scale;
            float mnew = fmaxf(fmaxf(m, fmaxf(s0, s1)), fmaxf(s2, s3));
            float c  = __expf(m - mnew);
            float p0 = __expf(s0 - mnew);
            float p1 = __expf(s1 - mnew);
            float p2 = __expf(s2 - mnew);
            float p3 = __expf(s3 - mnew);
            const float* vp = kp + DD;
            float2 v0 = *(const float2*)(vp);
            float2 v1 = *(const float2*)(vp + kstride);
            float2 v2 = *(const float2*)(vp + 2 * kstride);
            float2 v3 = *(const float2*)(vp + 3 * kstride);
            dsum = dsum * c + (p0 + p1) + (p2 + p3);
            a.x = a.x * c + p0 * v0.x + p1 * v1.x + p2 * v2.x + p3 * v3.x;
            a.y = a.y * c + p0 * v0.y + p1 * v1.y + p2 * v2.y + p3 * v3.y;
            m = mnew;
        }
        for (; j <= hi; j++) {
            const float* kp = base + (size_t)j * kstride + DD + h * DH + 2 * lane;
            float2 k0 = *(const float2*)(kp);
            float s0 = q.x * k0.x + q.y * k0.y;
            #pragma unroll
            for (int o = 16; o > 0; o >>= 1)
                s0 += __shfl_xor_sync(0xffffffffu, s0, o);
            s0 *= scale;
            float mnew = fmaxf(m, s0);
            float c  = __expf(m - mnew);
            float p0 = __expf(s0 - mnew);
            float2 v0 = *(const float2*)(kp + DD);
            dsum = dsum * c + p0;
            a.x = a.x * c + p0 * v0.x;
            a.y = a.y * c + p0 * v0.y;
            m = mnew;
        }
    }

    float inv = 1.0f / dsum;
    float* orow = out + ((size_t)(b * LL + i)) * DD + h * DH;
    *(float2*)(orow + 2 * lane) = make_float2(a.x * inv, a.y * inv);
}

// ---------------------------------------------------------------------------
// Launch
// ---------------------------------------------------------------------------
extern "C" void kernel_launch(void* const* d_in, const int* in_sizes, int n_in,
                              void* d_out, int out_size)
{
    const float* x     = (const float*)d_in[0];
    const float* in_w  = (const float*)d_in[1];
    const float* in_b  = (const float*)d_in[2];
    const float* out_w = (const float*)d_in[3];
    const float* out_b = (const float*)d_in[4];
    const float* ln1g  = (const float*)d_in[5];
    const float* ln1b  = (const float*)d_in[6];
    const float* ln2g  = (const float*)d_in[7];
    const float* ln2b  = (const float*)d_in[8];
    const float* w1    = (const float*)d_in[9];
    const float* b1    = (const float*)d_in[10];
    const float* w2    = (const float*)d_in[11];
    const float* b2    = (const float*)d_in[12];
    float* out = (float*)d_out;

    float *x2, *qkv, *attn, *xres, *hln, *ffn;
    cudaGetSymbolAddress((void**)&x2,   g_x2);
    cudaGetSymbolAddress((void**)&qkv,  g_qkv);
    cudaGetSymbolAddress((void**)&attn, g_attn);
    cudaGetSymbolAddress((void**)&xres, g_xres);
    cudaGetSymbolAddress((void**)&hln,  g_hln);
    cudaGetSymbolAddress((void**)&ffn,  g_ffn);

    int gy = (NROWS + 127) / 128;   // 65

    // 1. LN1
    ln_kernel<<<NROWS, 128>>>(x, ln1g, ln1b, x2);
    // 2. QKV = x2 @ in_w^T + in_b
    mma_gemm<0><<<dim3((3 * DD) / 128, gy), 256>>>(
        x2, in_w, in_b, nullptr, qkv, NROWS, 3 * DD, DD);
    // 3. attention
    attn_kernel<<<dim3(BB * HH, LL / 8), 256>>>(qkv, attn);
    // 4. xres = attn @ out_w^T + out_b + x
    mma_gemm<0><<<dim3(DD / 128, gy), 256>>>(
        attn, out_w, out_b, x, xres, NROWS, DD, DD);
    // 5. LN2
    ln_kernel<<<NROWS, 128>>>(xres, ln2g, ln2b, hln);
    // 6. ffn = gelu(hln @ w1^T + b1)
    mma_gemm<1><<<dim3(DFF / 128, gy), 256>>>(
        hln, w1, b1, nullptr, ffn, NROWS, DFF, DD);
    // 7. out = ffn @ w2^T + b2 + xres
    mma_gemm<0><<<dim3(DD / 128, gy), 256>>>(
        ffn, w2, b2, xres, out, NROWS, DD, DFF);
}

// round 9
// speedup vs baseline: 1.3239x; 1.3239x over previous
#include <cuda_runtime.h>
#include <cuda_bf16.h>
#include <math.h>

// Problem constants (fixed by the reference)
#define BB   4
#define TT   2048
#define MM   16
#define DD   512
#define HH   8
#define DFF  2048
#define WIN  128
#define LL   (MM + TT)          // 2064
#define NROWS (BB * LL)         // 8256
#define DH   64

// ---------------------------------------------------------------------------
// Scratch
// ---------------------------------------------------------------------------
__device__ float g_x2  [(size_t)NROWS * DD];
__device__ float g_qkv [(size_t)NROWS * 3 * DD];
__device__ float g_attn[(size_t)NROWS * DD];
__device__ float g_xres[(size_t)NROWS * DD];
__device__ float g_hln [(size_t)NROWS * DD];
__device__ float g_ffn [(size_t)NROWS * DFF];

// ---------------------------------------------------------------------------
// LayerNorm over D=512. One block (128 threads) per row.
// ---------------------------------------------------------------------------
__global__ void ln_kernel(const float* __restrict__ x,
                          const float* __restrict__ g,
                          const float* __restrict__ b,
                          float* __restrict__ y)
{
    int row = blockIdx.x;
    int t = threadIdx.x;
    const float4* xr = (const float4*)(x + (size_t)row * DD);
    float4 v = xr[t];
    float s  = v.x + v.y + v.z + v.w;
    float ss = v.x*v.x + v.y*v.y + v.z*v.z + v.w*v.w;

    int lane = t & 31, wid = t >> 5;
    #pragma unroll
    for (int o = 16; o > 0; o >>= 1) {
        s  += __shfl_xor_sync(0xffffffffu, s,  o);
        ss += __shfl_xor_sync(0xffffffffu, ss, o);
    }
    __shared__ float sh[8];
    if (lane == 0) { sh[wid] = s; sh[wid + 4] = ss; }
    __syncthreads();
    s  = sh[0] + sh[1] + sh[2] + sh[3];
    ss = sh[4] + sh[5] + sh[6] + sh[7];

    float mu  = s * (1.0f / DD);
    float var = ss * (1.0f / DD) - mu * mu;
    float inv = rsqrtf(var + 1e-5f);

    float4 gg = ((const float4*)g)[t];
    float4 bb = ((const float4*)b)[t];
    float4 o4;
    o4.x = (v.x - mu) * inv * gg.x + bb.x;
    o4.y = (v.y - mu) * inv * gg.y + bb.y;
    o4.z = (v.z - mu) * inv * gg.z + bb.z;
    o4.w = (v.w - mu) * inv * gg.w + bb.w;
    ((float4*)(y + (size_t)row * DD))[t] = o4;
}

// ---------------------------------------------------------------------------
// TF32 tensor-core GEMM (fast-tf32: raw fp32 bits, HW truncates to tf32).
// C[N,Mo] = A[N,K] @ W[Mo,K]^T + bias (+res) (+gelu)
// Block tile 128x128, BK=32, 256 threads (8 warps 2x4, warp tile 64x32),
// mma.sync.m16n8k8. 2-stage cp.async ring, ONE __syncthreads per k-slab.
// Rows padded to 36 floats: cp.async quarter-warp stores hit one contiguous
// 128B row segment; scalar fragment LDS banks = lq*4+lk (conflict-free).
// ---------------------------------------------------------------------------
#define LDR   36
#define TSZ   (128 * LDR)                  // floats per tensor per stage
#define GEMM_SMEM_BYTES (4 * TSZ * 4)      // A0,A1,W0,W1 = 73728 bytes

__device__ __forceinline__ void mma_tf32(float* c, const unsigned* a, const unsigned* b) {
    asm volatile(
        "mma.sync.aligned.m16n8k8.row.col.f32.tf32.tf32.f32 "
        "{%0,%1,%2,%3}, {%4,%5,%6,%7}, {%8,%9}, {%0,%1,%2,%3};"
        : "+f"(c[0]), "+f"(c[1]), "+f"(c[2]), "+f"(c[3])
        : "r"(a[0]), "r"(a[1]), "r"(a[2]), "r"(a[3]), "r"(b[0]), "r"(b[1]));
}

__device__ __forceinline__ void cp16(float* dst, const float* src, bool valid) {
    unsigned sa = (unsigned)__cvta_generic_to_shared(dst);
    int sz = valid ? 16 : 0;                // sz=0 -> 16B of zero-fill
    asm volatile("cp.async.cg.shared.global [%0], [%1], 16, %2;\n"
                 :: "r"(sa), "l"(src), "r"(sz));
}
#define CP_COMMIT() asm volatile("cp.async.commit_group;\n" ::: "memory")
#define CP_WAIT0()  asm volatile("cp.async.wait_group 0;\n" ::: "memory")

template<int ACT>
__global__ __launch_bounds__(256, 2) void mma_gemm(
    const float* __restrict__ A,
    const float* __restrict__ W,
    const float* __restrict__ bias,
    const float* __restrict__ res,
    float* __restrict__ C,
    int N, int Mo, int K)
{
    extern __shared__ float sm[];
    // stage s: A at sm + s*TSZ, W at sm + 2*TSZ + s*TSZ

    int tid  = threadIdx.x;
    int lane = tid & 31;
    int wid  = tid >> 5;
    int wm   = wid >> 2;          // 0..1
    int wn   = wid & 3;           // 0..3
    int n0   = blockIdx.y * 128;
    int m0   = blockIdx.x * 128;

    int lr = tid >> 3;            // 0..31 (staging row group)
    int lc = (tid & 7) * 4;       // 0..28 (k-col within 32)

    const float* Ag = A + (size_t)(n0 + lr) * K + lc;
    const float* Wg = W + (size_t)(m0 + lr) * K + lc;
    bool av[4];
    #pragma unroll
    for (int q = 0; q < 4; q++) av[q] = (n0 + lr + 32 * q) < N;

    float acc[4][4][4];
    #pragma unroll
    for (int i = 0; i < 4; i++)
        #pragma unroll
        for (int j = 0; j < 4; j++)
            #pragma unroll
            for (int q = 0; q < 4; q++) acc[i][j][q] = 0.0f;

    int nIter = K >> 5;           // K/32
    int lq = lane >> 2;           // 0..7
    int lk = lane & 3;            // 0..3

    // issue one full stage (A 4 rows-groups + W 4) into slot s for k-offset k0
    #define ISSUE_STAGE(slot, k0)                                             \
    {                                                                         \
        float* sa_ = sm + (slot) * TSZ;                                       \
        float* sw_ = sm + 2 * TSZ + (slot) * TSZ;                             \
        _Pragma("unroll")                                                     \
        for (int q = 0; q < 4; q++) {                                         \
            cp16(sa_ + (lr + 32 * q) * LDR + lc, Ag + (size_t)(32 * q) * K + (k0), av[q]); \
            cp16(sw_ + (lr + 32 * q) * LDR + lc, Wg + (size_t)(32 * q) * K + (k0), true);  \
        }                                                                     \
    }

    // prologue: stage 0 -> slot 0
    ISSUE_STAGE(0, 0)
    CP_COMMIT();

    for (int it = 0; it < nIter; it++) {
        CP_WAIT0();               // stage it complete (this thread)
        __syncthreads();          // publish stage it; everyone done reading slot it&1's old data

        if (it + 1 < nIter) {
            ISSUE_STAGE((it + 1) & 1, (it + 1) << 5)
        }
        CP_COMMIT();

        const float* sa = sm + (it & 1) * TSZ;
        const float* sw = sm + 2 * TSZ + (it & 1) * TSZ;

        #pragma unroll
        for (int ks = 0; ks < 4; ks++) {
            int kb = ks * 8;
            unsigned af[4][4];
            unsigned bf[4][2];
            #pragma unroll
            for (int am = 0; am < 4; am++) {
                int mr = wm * 64 + am * 16 + lq;
                af[am][0] = __float_as_uint(sa[mr * LDR + kb + lk]);
                af[am][1] = __float_as_uint(sa[(mr + 8) * LDR + kb + lk]);
                af[am][2] = __float_as_uint(sa[mr * LDR + kb + lk + 4]);
                af[am][3] = __float_as_uint(sa[(mr + 8) * LDR + kb + lk + 4]);
            }
            #pragma unroll
            for (int an = 0; an < 4; an++) {
                int nr = wn * 32 + an * 8 + lq;
                bf[an][0] = __float_as_uint(sw[nr * LDR + kb + lk]);
                bf[an][1] = __float_as_uint(sw[nr * LDR + kb + lk + 4]);
            }
            #pragma unroll
            for (int am = 0; am < 4; am++)
                #pragma unroll
                for (int an = 0; an < 4; an++)
                    mma_tf32(acc[am][an], af[am], bf[an]);
        }
    }
    #undef ISSUE_STAGE

    // epilogue
    #pragma unroll
    for (int am = 0; am < 4; am++) {
        #pragma unroll
        for (int an = 0; an < 4; an++) {
            int r0 = n0 + wm * 64 + am * 16 + lq;
            int c0 = m0 + wn * 32 + an * 8 + lk * 2;
            float b0 = bias[c0], b1 = bias[c0 + 1];
            #pragma unroll
            for (int half = 0; half < 2; half++) {
                int row = r0 + half * 8;
                if (row < N) {
                    float u0 = acc[am][an][half * 2 + 0] + b0;
                    float u1 = acc[am][an][half * 2 + 1] + b1;
                    if (ACT == 1) {
                        u0 = 0.5f * u0 * (1.0f + erff(u0 * 0.70710678118654752f));
                        u1 = 0.5f * u1 * (1.0f + erff(u1 * 0.70710678118654752f));
                    }
                    if (res) {
                        const float2 rr = *(const float2*)(res + (size_t)row * Mo + c0);
                        u0 += rr.x; u1 += rr.y;
                    }
                    *(float2*)(C + (size_t)row * Mo + c0) = make_float2(u0, u1);
                }
            }
        }
    }
}

// ---------------------------------------------------------------------------
// Banded attention. One warp per (b,h,query). Online softmax, 4 keys/iter,
// float2 accesses.
// ---------------------------------------------------------------------------
__global__ void attn_kernel(const float* __restrict__ qkv,
                            float* __restrict__ out)
{
    int lane = threadIdx.x & 31;
    int wid  = threadIdx.x >> 5;
    int bh = blockIdx.x;
    int b = bh >> 3;
    int h = bh & 7;
    int i = blockIdx.y * 8 + wid;
    if (i >= LL) return;

    const float* base = qkv + (size_t)b * LL * (3 * DD);
    float2 q = *(const float2*)(base + (size_t)i * (3 * DD) + h * DH + 2 * lane);

    float m = -1e30f, dsum = 0.0f;
    float2 a = make_float2(0.f, 0.f);
    const float scale = 0.125f;           // 1/sqrt(64)

    int rA_lo, rA_hi, rB_lo, rB_hi;       // inclusive
    if (i < MM) {
        rA_lo = 0; rA_hi = i;
        rB_lo = 1; rB_hi = 0;             // empty
    } else {
        rA_lo = 0; rA_hi = MM - 1;
        rB_lo = (i - WIN + 1 > MM) ? (i - WIN + 1) : MM;
        rB_hi = i;
    }

    const int kstride = 3 * DD;
    for (int r = 0; r < 2; r++) {
        int lo = (r == 0) ? rA_lo : rB_lo;
        int hi = (r == 0) ? rA_hi : rB_hi;
        int j = lo;
        for (; j + 3 <= hi; j += 4) {
            const float* kp = base + (size_t)j * kstride + DD + h * DH + 2 * lane;
            float2 k0 = *(const float2*)(kp);
            float2 k1 = *(const float2*)(kp + kstride);
            float2 k2 = *(const float2*)(kp + 2 * kstride);
            float2 k3 = *(const float2*)(kp + 3 * kstride);
            float s0 = q.x * k0.x + q.y * k0.y;
            float s1 = q.x * k1.x + q.y * k1.y;
            float s2 = q.x * k2.x + q.y * k2.y;
            float s3 = q.x * k3.x + q.y * k3.y;
            #pragma unroll
            for (int o = 16; o > 0; o >>= 1) {
                s0 += __shfl_xor_sync(0xffffffffu, s0, o);
                s1 += __shfl_xor_sync(0xffffffffu, s1, o);
                s2 += __shfl_xor_sync(0xffffffffu, s2, o);
                s3 += __shfl_xor_sync(0xffffffffu, s3, o);
            }
            s0 *= scale; s1 *= scale; s2 *= scale; s3 *= scale;
            float mnew = fmaxf(fmaxf(m, fmaxf(s0, s1)), fmaxf(s2, s3));
            float c  = __expf(m - mnew);
            float p0 = __expf(s0 - mnew);
            float p1 = __expf(s1 - mnew);
            float p2 = __expf(s2 - mnew);
            float p3 = __expf(s3 - mnew);
            const float* vp = kp + DD;
            float2 v0 = *(const float2*)(vp);
            float2 v1 = *(const float2*)(vp + kstride);
            float2 v2 = *(const float2*)(vp + 2 * kstride);
            float2 v3 = *(const float2*)(vp + 3 * kstride);
            dsum = dsum * c + (p0 + p1) + (p2 + p3);
            a.x = a.x * c + p0 * v0.x + p1 * v1.x + p2 * v2.x + p3 * v3.x;
            a.y = a.y * c + p0 * v0.y + p1 * v1.y + p2 * v2.y + p3 * v3.y;
            m = mnew;
        }
        for (; j <= hi; j++) {
            const float* kp = base + (size_t)j * kstride + DD + h * DH + 2 * lane;
            float2 k0 = *(const float2*)(kp);
            float s0 = q.x * k0.x + q.y * k0.y;
            #pragma unroll
            for (int o = 16; o > 0; o >>= 1)
                s0 += __shfl_xor_sync(0xffffffffu, s0, o);
            s0 *= scale;
            float mnew = fmaxf(m, s0);
            float c  = __expf(m - mnew);
            float p0 = __expf(s0 - mnew);
            float2 v0 = *(const float2*)(kp + DD);
            dsum = dsum * c + p0;
            a.x = a.x * c + p0 * v0.x;
            a.y = a.y * c + p0 * v0.y;
            m = mnew;
        }
    }

    float inv = 1.0f / dsum;
    float* orow = out + ((size_t)(b * LL + i)) * DD + h * DH;
    *(float2*)(orow + 2 * lane) = make_float2(a.x * inv, a.y * inv);
}

// ---------------------------------------------------------------------------
// Launch
// ---------------------------------------------------------------------------
extern "C" void kernel_launch(void* const* d_in, const int* in_sizes, int n_in,
                              void* d_out, int out_size)
{
    const float* x     = (const float*)d_in[0];
    const float* in_w  = (const float*)d_in[1];
    const float* in_b  = (const float*)d_in[2];
    const float* out_w = (const float*)d_in[3];
    const float* out_b = (const float*)d_in[4];
    const float* ln1g  = (const float*)d_in[5];
    const float* ln1b  = (const float*)d_in[6];
    const float* ln2g  = (const float*)d_in[7];
    const float* ln2b  = (const float*)d_in[8];
    const float* w1    = (const float*)d_in[9];
    const float* b1    = (const float*)d_in[10];
    const float* w2    = (const float*)d_in[11];
    const float* b2    = (const float*)d_in[12];
    float* out = (float*)d_out;

    float *x2, *qkv, *attn, *xres, *hln, *ffn;
    cudaGetSymbolAddress((void**)&x2,   g_x2);
    cudaGetSymbolAddress((void**)&qkv,  g_qkv);
    cudaGetSymbolAddress((void**)&attn, g_attn);
    cudaGetSymbolAddress((void**)&xres, g_xres);
    cudaGetSymbolAddress((void**)&hln,  g_hln);
    cudaGetSymbolAddress((void**)&ffn,  g_ffn);

    cudaFuncSetAttribute(mma_gemm<0>, cudaFuncAttributeMaxDynamicSharedMemorySize, GEMM_SMEM_BYTES);
    cudaFuncSetAttribute(mma_gemm<1>, cudaFuncAttributeMaxDynamicSharedMemorySize, GEMM_SMEM_BYTES);

    int gy = (NROWS + 127) / 128;   // 65

    // 1. LN1
    ln_kernel<<<NROWS, 128>>>(x, ln1g, ln1b, x2);
    // 2. QKV = x2 @ in_w^T + in_b
    mma_gemm<0><<<dim3((3 * DD) / 128, gy), 256, GEMM_SMEM_BYTES>>>(
        x2, in_w, in_b, nullptr, qkv, NROWS, 3 * DD, DD);
    // 3. attention
    attn_kernel<<<dim3(BB * HH, LL / 8), 256>>>(qkv, attn);
    // 4. xres = attn @ out_w^T + out_b + x
    mma_gemm<0><<<dim3(DD / 128, gy), 256, GEMM_SMEM_BYTES>>>(
        attn, out_w, out_b, x, xres, NROWS, DD, DD);
    // 5. LN2
    ln_kernel<<<NROWS, 128>>>(xres, ln2g, ln2b, hln);
    // 6. ffn = gelu(hln @ w1^T + b1)
    mma_gemm<1><<<dim3(DFF / 128, gy), 256, GEMM_SMEM_BYTES>>>(
        hln, w1, b1, nullptr, ffn, NROWS, DFF, DD);
    // 7. out = ffn @ w2^T + b2 + xres
    mma_gemm<0><<<dim3(DD / 128, gy), 256, GEMM_SMEM_BYTES>>>(
        ffn, w2, b2, xres, out, NROWS, DD, DFF);
}